// round 10
// baseline (speedup 1.0000x reference)
#include <cuda_runtime.h>
#include <cuda_fp16.h>
#include <math.h>
#include <stdint.h>

// Shapes (fixed)
#define HW_DIM  1024
#define C_DIM   256
#define N_TOK   32768
#define K_CODES 1024
#define Z_ELEMS 8388608
#define BETA_F  0.25f
#define MARGIN  0.03f

// phase1 tiling: CTA = 128 tokens x 1024 codes; 16 chunks of 64 codes
#define MT      128
#define NCTA    (N_TOK / MT)     // 256
#define CHUNKS  16
#define KSTEPS  16

// phase1 smem (bytes)
#define AROWB   528              // 264 halves (528%128=16, ldsm clean)
#define AH_OFF  0                // 128*528 = 67584
#define RING_OFF 67584           // 2 slots x 65536 (64 codes x 1024B)
#define RSLOT   65536
#define NS_OFF  198656           // 1024 floats -> 202752
#define SMEM_TOTAL 202752
// post-mainloop scratch aliases the ring:
#define CV_OFF  RING_OFF                 // 256 floats
#define CI_OFF  (RING_OFF + 1024)        // 256 ints
#define C2_OFF  (RING_OFF + 2048)        // 256 floats
#define KF_OFF  (RING_OFF + 3072)        // 128 ints
#define RED_OFF (RING_OFF + 3584)        // 256 floats

static __device__ int    g_counts[K_CODES];
static __device__ float  g_norms[K_CODES];
static __device__ float  g_partials[NCTA];
static __device__ float  g_loss2[N_TOK];
static __device__ int    g_nflag;
static __device__ int    g_flaglist[N_TOK];
// pre-split codebook: row = 1024B = 32 k-blocks of [hi x8 | lo x8] halves
static __device__ __half g_cbi[K_CODES * 512];

// ---------------------------------------------------------------------------
__device__ __forceinline__ uint32_t smem_u32(const void* p) {
    uint32_t a;
    asm("{ .reg .u64 T; cvta.to.shared.u64 T, %1; cvt.u32.u64 %0, T; }"
        : "=r"(a) : "l"(p));
    return a;
}
__device__ __forceinline__ void ldsm4(uint32_t addr, uint32_t r[4]) {
    asm volatile("ldmatrix.sync.aligned.m8n8.x4.shared.b16 {%0,%1,%2,%3}, [%4];"
                 : "=r"(r[0]), "=r"(r[1]), "=r"(r[2]), "=r"(r[3]) : "r"(addr));
}
__device__ __forceinline__ void mma_f16(float c[4], const uint32_t a[4],
                                        uint32_t b0, uint32_t b1) {
    asm volatile(
        "mma.sync.aligned.m16n8k16.row.col.f32.f16.f16.f32 "
        "{%0,%1,%2,%3}, {%4,%5,%6,%7}, {%8,%9}, {%0,%1,%2,%3};"
        : "+f"(c[0]), "+f"(c[1]), "+f"(c[2]), "+f"(c[3])
        : "r"(a[0]), "r"(a[1]), "r"(a[2]), "r"(a[3]), "r"(b0), "r"(b1));
}
#define CP_ASYNC16(dst, src) \
    asm volatile("cp.async.cg.shared.global [%0], [%1], 16;" :: "r"(dst), "l"(src))
#define CP_COMMIT() asm volatile("cp.async.commit_group;" ::: "memory")
#define CP_WAIT1()  asm volatile("cp.async.wait_group 1;" ::: "memory")
#define CP_WAIT0()  asm volatile("cp.async.wait_group 0;" ::: "memory")

// ---------------------------------------------------------------------------
// prep: interleaved hi/lo codebook + norms + zero counts/loss2/nflag
__global__ void prep_kernel(const float* __restrict__ cb) {
    __shared__ float red[8];
    const int code = blockIdx.x;
    const int c    = threadIdx.x;
    float v = cb[code * C_DIM + c];
    __half hi = __float2half_rn(v);
    __half lo = __float2half_rn(v - __half2float(hi));
    int base = code * 512 + (c >> 3) * 16 + (c & 7);
    g_cbi[base]     = hi;
    g_cbi[base + 8] = lo;
    if (c < 32) g_loss2[code * 32 + c] = 0.f;
    float s = v * v;
    #pragma unroll
    for (int off = 16; off > 0; off >>= 1)
        s += __shfl_down_sync(0xffffffffu, s, off);
    if ((c & 31) == 0) red[c >> 5] = s;
    __syncthreads();
    if (c == 0) {
        float t = 0.f;
        #pragma unroll
        for (int i = 0; i < 8; i++) t += red[i];
        g_norms[code]  = t;
        g_counts[code] = 0;
        if (code == 0) g_nflag = 0;
    }
}

// ---------------------------------------------------------------------------
// phase 1: 2-term split-fp16 GEMM-argmin + margin test + fused gather.
// 8 warps = 4 token-groups x 2 code-groups; warp tile = 32 tok x 32 codes.
__global__ __launch_bounds__(256, 1)
void phase1_kernel(const float* __restrict__ z, const float* __restrict__ cb,
                   float* __restrict__ out) {
    extern __shared__ char smem[];
    const uint32_t sb = smem_u32(smem);
    float* ns = (float*)(smem + NS_OFF);

    const int tid  = threadIdx.x;
    const int warp = tid >> 5;
    const int lane = tid & 31;
    const int tg   = warp & 3;       // token group (32 tokens)
    const int cg   = warp >> 2;      // code half of 64-chunk (32 codes)
    const int g    = lane >> 2;
    const int t    = lane & 3;

    const int n0  = blockIdx.x * MT;
    const int b   = n0 >> 10;
    const int hw0 = n0 & 1023;
    const float* zb = z + (size_t)b * (C_DIM * HW_DIM) + hw0;

    // ---- B prefetch: chunk = 64 codes x 1024B rows, XOR-swizzled ----------
    auto prefetch = [&](int p) {
        const char* src = (const char*)g_cbi + (size_t)p * RSLOT;
        uint32_t dst0 = sb + RING_OFF + (uint32_t)((p & 1) * RSLOT);
        #pragma unroll
        for (int it = 0; it < 16; it++) {
            int i    = it * 256 + tid;
            int code = i >> 6;
            int seg  = i & 63;
            uint32_t dst = dst0 + (uint32_t)(code * 1024 + ((seg ^ (code & 7)) << 4));
            CP_ASYNC16(dst, src + (size_t)i * 16);
        }
    };
    prefetch(0); CP_COMMIT();
    prefetch(1); CP_COMMIT();

    // ---- stage A (hi only), coalesced over tokens -------------------------
    for (int it = 0; it < 128; it++) {
        int i  = it * 256 + tid;
        int tk = i & 127;
        int c  = i >> 7;
        *(__half*)(smem + AH_OFF + tk * AROWB + c * 2) =
            __float2half_rn(zb[(size_t)c * HW_DIM + tk]);
    }
    #pragma unroll
    for (int it = 0; it < 4; it++) ns[it * 256 + tid] = g_norms[it * 256 + tid];

    const uint32_t aH = sb + AH_OFF
        + (uint32_t)((tg * 32 + (lane & 15)) * AROWB + (lane >> 4) * 16);
    const int bcode = lane & 7;
    const int bgrp  = lane >> 3;
    uint32_t brow[4];
    #pragma unroll
    for (int nb = 0; nb < 4; nb++)
        brow[nb] = (uint32_t)(cg * 32768 + (nb * 8 + bcode) * 1024);

    // 4 slots: mt(2) x rowhalf(2); (v1, i1, v2)
    float v1[4], v2[4];
    int   i1[4];
    #pragma unroll
    for (int s = 0; s < 4; s++) { v1[s] = 3.4e38f; v2[s] = 3.4e38f; i1[s] = 0; }

    for (int p = 0; p < CHUNKS; p++) {
        if (p == CHUNKS - 1) CP_WAIT0(); else CP_WAIT1();
        __syncthreads();

        const uint32_t pbase = sb + RING_OFF + (uint32_t)((p & 1) * RSLOT);

        float acc[2][4][4];
        #pragma unroll
        for (int mt = 0; mt < 2; mt++)
            #pragma unroll
            for (int nb = 0; nb < 4; nb++)
                #pragma unroll
                for (int q = 0; q < 4; q++) acc[mt][nb][q] = 0.f;

        #pragma unroll
        for (int ks = 0; ks < KSTEPS; ks++) {
            uint32_t ahf[2][4];
            #pragma unroll
            for (int mt = 0; mt < 2; mt++)
                ldsm4(aH + (uint32_t)(mt * 16 * AROWB + ks * 32), ahf[mt]);
            #pragma unroll
            for (int nb = 0; nb < 4; nb++) {
                // ldsm4 -> [bh k0-7][bl k0-7][bh k8-15][bl k8-15] for 8 codes
                uint32_t bb[4];
                ldsm4(pbase + brow[nb]
                      + (uint32_t)(((4 * ks + bgrp) ^ bcode) << 4), bb);
                #pragma unroll
                for (int mt = 0; mt < 2; mt++) {
                    mma_f16(acc[mt][nb], ahf[mt], bb[0], bb[2]);  // ah*bh
                    mma_f16(acc[mt][nb], ahf[mt], bb[1], bb[3]);  // ah*bl
                }
            }
        }

        __syncthreads();
        if (p + 2 < CHUNKS) { prefetch(p + 2); CP_COMMIT(); }

        // epilogue: dist = |e|^2 - 2*acc ; track best + second-best
        #pragma unroll
        for (int nb = 0; nb < 4; nb++) {
            int cl = cg * 32 + nb * 8 + 2 * t;
            int code0 = p * 64 + cl;
            float nk0 = ns[code0];
            float nk1 = ns[code0 + 1];
            #pragma unroll
            for (int mt = 0; mt < 2; mt++) {
                #pragma unroll
                for (int h = 0; h < 2; h++) {
                    int s = mt * 2 + h;
                    float d0 = nk0 - 2.f * acc[mt][nb][h * 2];
                    float d1 = nk1 - 2.f * acc[mt][nb][h * 2 + 1];
                    if (d0 < v1[s]) { v2[s] = v1[s]; v1[s] = d0; i1[s] = code0; }
                    else if (d0 < v2[s]) v2[s] = d0;
                    if (d1 < v1[s]) { v2[s] = v1[s]; v1[s] = d1; i1[s] = code0 + 1; }
                    else if (d1 < v2[s]) v2[s] = d1;
                }
            }
        }
    }

    // lane-reduce across t, merging (v1,i1,v2) triples
    #pragma unroll
    for (int s = 0; s < 4; s++) {
        #pragma unroll
        for (int m = 1; m <= 2; m <<= 1) {
            float ov1 = __shfl_xor_sync(0xffffffffu, v1[s], m);
            int   oi1 = __shfl_xor_sync(0xffffffffu, i1[s], m);
            float ov2 = __shfl_xor_sync(0xffffffffu, v2[s], m);
            if (ov1 < v1[s] || (ov1 == v1[s] && oi1 < i1[s])) {
                v2[s] = fminf(v1[s], ov2); v1[s] = ov1; i1[s] = oi1;
            } else {
                v2[s] = fminf(v2[s], ov1);
            }
        }
    }

    float* candv = (float*)(smem + CV_OFF);
    int*   candi = (int*)(smem + CI_OFF);
    float* cand2 = (float*)(smem + C2_OFF);
    int*   kf    = (int*)(smem + KF_OFF);
    if (t == 0) {
        #pragma unroll
        for (int s = 0; s < 4; s++) {
            int mt = s >> 1, h = s & 1;
            int tok = tg * 32 + mt * 16 + h * 8 + g;
            candv[tok * 2 + cg] = v1[s];
            candi[tok * 2 + cg] = i1[s];
            cand2[tok * 2 + cg] = v2[s];
        }
    }
    __syncthreads();
    if (tid < MT) {
        float a1 = candv[tid * 2], b1v = candv[tid * 2 + 1];
        int   ai = candi[tid * 2], bi  = candi[tid * 2 + 1];
        float a2 = cand2[tid * 2], b2  = cand2[tid * 2 + 1];
        float V1, V2; int I1;
        if (b1v < a1 || (b1v == a1 && bi < ai)) {
            V1 = b1v; I1 = bi; V2 = fminf(a1, b2);
        } else {
            V1 = a1; I1 = ai; V2 = fminf(a2, b1v);
        }
        if (V2 - V1 >= MARGIN) {
            kf[tid] = I1;
            atomicAdd(&g_counts[I1], 1);
        } else {
            kf[tid] = -1;
            int pos = atomicAdd(&g_nflag, 1);
            g_flaglist[pos] = n0 + tid;
        }
    }
    __syncthreads();

    // fused gather + loss for confident tokens (thread per token)
    {
        const int k = kf[tid & 127];
        const int tok = tid & 127;
        const int ch0 = (tid >> 7) * 128;
        float s = 0.f;
        if (k >= 0) {
            const float4* crow = (const float4*)(cb + (size_t)k * C_DIM + ch0);
            const float* zp = zb + (size_t)ch0 * HW_DIM + tok;
            float* op = out + (size_t)b * (C_DIM * HW_DIM) + hw0
                            + (size_t)ch0 * HW_DIM + tok;
            #pragma unroll 8
            for (int j = 0; j < 32; j++) {
                float4 e = crow[j];
                int c = j * 4;
                float d0 = e.x - zp[(c + 0) * HW_DIM];
                float d1 = e.y - zp[(c + 1) * HW_DIM];
                float d2 = e.z - zp[(c + 2) * HW_DIM];
                float d3 = e.w - zp[(c + 3) * HW_DIM];
                s += d0 * d0 + d1 * d1 + d2 * d2 + d3 * d3;
                op[(c + 0) * HW_DIM] = e.x;
                op[(c + 1) * HW_DIM] = e.y;
                op[(c + 2) * HW_DIM] = e.z;
                op[(c + 3) * HW_DIM] = e.w;
            }
        }
        float* red = (float*)(smem + RED_OFF);
        red[tid] = s;
        __syncthreads();
        for (int off = 128; off > 0; off >>= 1) {
            if (tid < off) red[tid] += red[tid + off];
            __syncthreads();
        }
        if (tid == 0) g_partials[blockIdx.x] = red[0];
    }
}

// ---------------------------------------------------------------------------
// phase 2: exact fp32 argmin + gather + loss for flagged tokens.
// Each CTA streams the codebook ONCE per group of 8 tokens.
__global__ __launch_bounds__(256)
void phase2_kernel(const float* __restrict__ z, const float* __restrict__ cb,
                   float* __restrict__ out) {
    __shared__ float zs[8 * 264];
    __shared__ float cbs[32 * 264];
    const int tid  = threadIdx.x;
    const int warp = tid >> 5;
    const int lane = tid & 31;
    const int nf   = g_nflag;

    for (int g0 = blockIdx.x * 8; g0 < nf; g0 += gridDim.x * 8) {
        int myTok = (g0 + warp < nf) ? g_flaglist[g0 + warp] : -1;
        __syncthreads();
        if (myTok >= 0) {
            int tb = myTok >> 10, thw = myTok & 1023;
            const float* zp = z + (size_t)tb * (C_DIM * HW_DIM) + thw;
            #pragma unroll
            for (int j = 0; j < 8; j++)
                zs[warp * 264 + lane + 32 * j] = zp[(size_t)(lane + 32 * j) * HW_DIM];
        }

        float bv = 3.4e38f;
        int   bi = 0;
        for (int ch = 0; ch < 32; ch++) {
            __syncthreads();
            #pragma unroll
            for (int it = 0; it < 32; it++) {
                int i = it * 256 + tid;
                int r = i >> 8, c = i & 255;
                cbs[r * 264 + c] = cb[(size_t)(ch * 32 + r) * C_DIM + c];
            }
            __syncthreads();
            if (myTok >= 0) {
                const float4* cr = (const float4*)(cbs + lane * 264);
                const float4* zr = (const float4*)(zs + warp * 264);
                float dot = 0.f;
                #pragma unroll 16
                for (int c4 = 0; c4 < 64; c4++) {
                    float4 e = cr[c4];
                    float4 zz = zr[c4];
                    dot += e.x * zz.x + e.y * zz.y + e.z * zz.z + e.w * zz.w;
                }
                int code = ch * 32 + lane;
                float d = g_norms[code] - 2.f * dot;
                if (d < bv || (d == bv && code < bi)) { bv = d; bi = code; }
            }
        }
        __syncthreads();

        if (myTok >= 0) {
            #pragma unroll
            for (int m = 16; m > 0; m >>= 1) {
                float ov = __shfl_xor_sync(0xffffffffu, bv, m);
                int   oi = __shfl_xor_sync(0xffffffffu, bi, m);
                if (ov < bv || (ov == bv && oi < bi)) { bv = ov; bi = oi; }
            }
            if (lane == 0) atomicAdd(&g_counts[bi], 1);

            int tb = myTok >> 10, thw = myTok & 1023;
            const float* zp = z + (size_t)tb * (C_DIM * HW_DIM) + thw;
            float* op = out + (size_t)tb * (C_DIM * HW_DIM) + thw;
            const float4* crow = (const float4*)(cb + (size_t)bi * C_DIM);
            float ls = 0.f;
            #pragma unroll
            for (int jj = 0; jj < 2; jj++) {
                int c4 = lane + jj * 32;
                float4 e = crow[c4];
                int c = c4 * 4;
                float d0 = e.x - zp[(c + 0) * HW_DIM];
                float d1 = e.y - zp[(c + 1) * HW_DIM];
                float d2 = e.z - zp[(c + 2) * HW_DIM];
                float d3 = e.w - zp[(c + 3) * HW_DIM];
                ls += d0 * d0 + d1 * d1 + d2 * d2 + d3 * d3;
                op[(c + 0) * HW_DIM] = e.x;
                op[(c + 1) * HW_DIM] = e.y;
                op[(c + 2) * HW_DIM] = e.z;
                op[(c + 3) * HW_DIM] = e.w;
            }
            #pragma unroll
            for (int m = 16; m > 0; m >>= 1)
                ls += __shfl_xor_sync(0xffffffffu, ls, m);
            if (lane == 0) g_loss2[myTok] = ls;
        }
    }
}

// ---------------------------------------------------------------------------
__global__ void finalize_kernel(float* __restrict__ out, int out_size) {
    __shared__ float s1[1024];
    __shared__ float s2[1024];
    const int tid = threadIdx.x;
    float ls = (tid < NCTA) ? g_partials[tid] : 0.f;
    #pragma unroll
    for (int j = 0; j < 32; j++) ls += g_loss2[tid * 32 + j];
    float p  = (float)g_counts[tid] * (1.0f / (float)N_TOK);
    float pc = fmaxf(p, 1e-10f);
    s1[tid] = ls;
    s2[tid] = pc * logf(pc);
    __syncthreads();
    for (int off = 512; off > 0; off >>= 1) {
        if (tid < off) { s1[tid] += s1[tid + off]; s2[tid] += s2[tid + off]; }
        __syncthreads();
    }
    if (tid == 0) {
        float mse = s1[0] * (1.0f / (float)Z_ELEMS);
        if (out_size >= Z_ELEMS + 1) out[Z_ELEMS]     = mse * (1.0f + BETA_F);
        if (out_size >= Z_ELEMS + 2) out[Z_ELEMS + 1] = expf(-s2[0]);
    }
}

// ---------------------------------------------------------------------------
extern "C" void kernel_launch(void* const* d_in, const int* in_sizes, int n_in,
                              void* d_out, int out_size) {
    const float* z  = (const float*)d_in[0];
    const float* cb = (const float*)d_in[1];
    float* out = (float*)d_out;

    cudaFuncSetAttribute(phase1_kernel,
                         cudaFuncAttributeMaxDynamicSharedMemorySize, SMEM_TOTAL);

    prep_kernel<<<K_CODES, 256>>>(cb);
    phase1_kernel<<<NCTA, 256, SMEM_TOTAL>>>(z, cb, out);
    phase2_kernel<<<64, 256>>>(z, cb, out);
    finalize_kernel<<<1, 1024>>>(out, out_size);
}

// round 11
// speedup vs baseline: 1.5546x; 1.5546x over previous
#include <cuda_runtime.h>
#include <cuda_fp16.h>
#include <math.h>
#include <stdint.h>

// Shapes (fixed)
#define HW_DIM  1024
#define C_DIM   256
#define N_TOK   32768
#define K_CODES 1024
#define Z_ELEMS 8388608
#define BETA_F  0.25f

// tiling (R4-identical)
#define MT      128            // tokens per CTA
#define NCH     64             // codes per chunk
#define CHUNKS  (K_CODES / NCH)
#define KSTEPS  (C_DIM / 16)   // 16

// fp16 split scale (R4-identical)
#define LO_S    2048.0f
#define LO_IS   4.8828125e-4f

// smem layout (bytes) — R4-identical + kf/red appended
#define ROWB    528
#define AH_OFF  0
#define AL_OFF  67584           // 128*528
#define BH_OFF  135168
#define BL_OFF  168960          // + 64*528
#define NS_OFF  202752          // 64 floats
#define CV_OFF  203008          // 128*2 floats
#define CI_OFF  204032          // 128*2 ints
#define KF_OFF  205056          // 128 ints
#define RED_OFF 205568          // 256 floats
#define SMEM_TOTAL 206592

#define NCTA    (N_TOK / MT)    // 256

static __device__ int   g_counts[K_CODES];
static __device__ float g_norms[K_CODES];
static __device__ float g_partials[NCTA];

// ---------------------------------------------------------------------------
__device__ __forceinline__ uint32_t smem_u32(const void* p) {
    uint32_t a;
    asm("{ .reg .u64 T; cvta.to.shared.u64 T, %1; cvt.u32.u64 %0, T; }"
        : "=r"(a) : "l"(p));
    return a;
}
__device__ __forceinline__ void ldsm4(uint32_t addr, uint32_t r[4]) {
    asm volatile("ldmatrix.sync.aligned.m8n8.x4.shared.b16 {%0,%1,%2,%3}, [%4];"
                 : "=r"(r[0]), "=r"(r[1]), "=r"(r[2]), "=r"(r[3]) : "r"(addr));
}
__device__ __forceinline__ void ldsm2(uint32_t addr, uint32_t r[2]) {
    asm volatile("ldmatrix.sync.aligned.m8n8.x2.shared.b16 {%0,%1}, [%2];"
                 : "=r"(r[0]), "=r"(r[1]) : "r"(addr));
}
__device__ __forceinline__ void mma_f16(float c[4], const uint32_t a[4],
                                        uint32_t b0, uint32_t b1) {
    asm volatile(
        "mma.sync.aligned.m16n8k16.row.col.f32.f16.f16.f32 "
        "{%0,%1,%2,%3}, {%4,%5,%6,%7}, {%8,%9}, {%0,%1,%2,%3};"
        : "+f"(c[0]), "+f"(c[1]), "+f"(c[2]), "+f"(c[3])
        : "r"(a[0]), "r"(a[1]), "r"(a[2]), "r"(a[3]), "r"(b0), "r"(b1));
}
__device__ __forceinline__ void split16(float a, __half& hi, __half& lo) {
    hi = __float2half_rn(a);
    lo = __float2half_rn((a - __half2float(hi)) * LO_S);
}

// ---------------------------------------------------------------------------
// prep: norms + zero counts (merged init)
__global__ void prep_kernel(const float* __restrict__ cb) {
    __shared__ float red[8];
    const int code = blockIdx.x;
    const int c    = threadIdx.x;
    float v = cb[code * C_DIM + c];
    float s = v * v;
    #pragma unroll
    for (int off = 16; off > 0; off >>= 1)
        s += __shfl_down_sync(0xffffffffu, s, off);
    if ((c & 31) == 0) red[c >> 5] = s;
    __syncthreads();
    if (c == 0) {
        float t = 0.f;
        #pragma unroll
        for (int i = 0; i < 8; i++) t += red[i];
        g_norms[code]  = t;
        g_counts[code] = 0;
    }
}

// ---------------------------------------------------------------------------
// R4 mainloop, verbatim, + fused gather/loss tail.
// CTA: 128 tokens x all 1024 codes (16 chunks of 64).
// 8 warps = 4 token-groups x 2 code-groups; warp tile = 32 tok x 32 codes.
__global__ __launch_bounds__(256, 1)
void argmin_fused(const float* __restrict__ z, const float* __restrict__ cb,
                  float* __restrict__ out) {
    extern __shared__ char smem[];
    const uint32_t sb = smem_u32(smem);
    float* ns    = (float*)(smem + NS_OFF);
    float* candv = (float*)(smem + CV_OFF);
    int*   candi = (int*)(smem + CI_OFF);
    int*   kf    = (int*)(smem + KF_OFF);
    float* red   = (float*)(smem + RED_OFF);

    const int tid  = threadIdx.x;
    const int warp = tid >> 5;
    const int lane = tid & 31;
    const int tg   = warp & 3;
    const int cg   = warp >> 2;
    const int g    = lane >> 2;
    const int t    = lane & 3;
    const int l15  = lane & 15;

    const int n0  = blockIdx.x * MT;
    const int b   = n0 >> 10;
    const int hw0 = n0 & 1023;
    const float* zb = z + (size_t)b * (C_DIM * HW_DIM) + hw0;
    const float4* cb4 = (const float4*)cb;

    // stage A (128 tok x 256 c) as fp16 hi/lo, coalesced over tokens
    for (int it = 0; it < 128; it++) {
        int i  = it * 256 + tid;
        int tk = i & 127;
        int c  = i >> 7;
        float a = zb[(size_t)c * HW_DIM + tk];
        __half hi, lo;
        split16(a, hi, lo);
        *(__half*)(smem + AH_OFF + tk * ROWB + c * 2) = hi;
        *(__half*)(smem + AL_OFF + tk * ROWB + c * 2) = lo;
    }

    const uint32_t aH  = sb + AH_OFF + (uint32_t)((tg * 32 + l15) * ROWB + (lane >> 4) * 16);
    const uint32_t aL  = aH + (uint32_t)(AL_OFF - AH_OFF);
    const uint32_t bHb = sb + BH_OFF + (uint32_t)((cg * 32 + (l15 & 7)) * ROWB + (l15 >> 3) * 16);
    const uint32_t bLb = bHb + (uint32_t)(BL_OFF - BH_OFF);

    float bestv4[4];
    int   besti4[4];
    #pragma unroll
    for (int s = 0; s < 4; s++) { bestv4[s] = 3.4e38f; besti4[s] = 0; }

    for (int ch = 0; ch < CHUNKS; ch++) {
        const int k0c = ch * NCH;
        __syncthreads();   // protect B from previous chunk's readers
        // stage B chunk (64 codes x 256 c) fp16 hi/lo
        #pragma unroll
        for (int it = 0; it < 16; it++) {
            int i    = it * 256 + tid;
            int code = i >> 6;
            int j4   = i & 63;
            float4 v = cb4[(size_t)(k0c + code) * 64 + j4];
            __half h0, l0, h1, l1, h2, l2, h3, l3;
            split16(v.x, h0, l0); split16(v.y, h1, l1);
            split16(v.z, h2, l2); split16(v.w, h3, l3);
            __half2 hA = __halves2half2(h0, h1), hB = __halves2half2(h2, h3);
            __half2 lA = __halves2half2(l0, l1), lB = __halves2half2(l2, l3);
            uint32_t off = (uint32_t)(code * ROWB + j4 * 8);
            *(uint2*)(smem + BH_OFF + off) = make_uint2(*(uint32_t*)&hA, *(uint32_t*)&hB);
            *(uint2*)(smem + BL_OFF + off) = make_uint2(*(uint32_t*)&lA, *(uint32_t*)&lB);
        }
        if (tid < NCH) ns[tid] = g_norms[k0c + tid];
        __syncthreads();

        float hh[2][4][4], md[2][4][4];
        #pragma unroll
        for (int mt = 0; mt < 2; mt++)
            #pragma unroll
            for (int nb = 0; nb < 4; nb++)
                #pragma unroll
                for (int q = 0; q < 4; q++) { hh[mt][nb][q] = 0.f; md[mt][nb][q] = 0.f; }

        #pragma unroll 4
        for (int ks = 0; ks < KSTEPS; ks++) {
            uint32_t ah[2][4], al[2][4];
            #pragma unroll
            for (int mt = 0; mt < 2; mt++) {
                ldsm4(aH + (uint32_t)(mt * 16 * ROWB + ks * 32), ah[mt]);
                ldsm4(aL + (uint32_t)(mt * 16 * ROWB + ks * 32), al[mt]);
            }
            #pragma unroll
            for (int nb = 0; nb < 4; nb++) {
                uint32_t bh[2], bl[2];
                ldsm2(bHb + (uint32_t)(nb * 8 * ROWB + ks * 32), bh);
                ldsm2(bLb + (uint32_t)(nb * 8 * ROWB + ks * 32), bl);
                #pragma unroll
                for (int mt = 0; mt < 2; mt++) {
                    mma_f16(hh[mt][nb], ah[mt], bh[0], bh[1]);
                    mma_f16(md[mt][nb], ah[mt], bl[0], bl[1]);
                    mma_f16(md[mt][nb], al[mt], bh[0], bh[1]);
                }
            }
        }

        // epilogue: dist = |e|^2 - 2 (hh + md/2048)
        #pragma unroll
        for (int nb = 0; nb < 4; nb++) {
            int cl = cg * 32 + nb * 8 + 2 * t;
            float nk0 = ns[cl];
            float nk1 = ns[cl + 1];
            int code0 = k0c + cl;
            #pragma unroll
            for (int mt = 0; mt < 2; mt++) {
                float d00 = nk0 - 2.f * (hh[mt][nb][0] + md[mt][nb][0] * LO_IS);
                float d01 = nk1 - 2.f * (hh[mt][nb][1] + md[mt][nb][1] * LO_IS);
                float d10 = nk0 - 2.f * (hh[mt][nb][2] + md[mt][nb][2] * LO_IS);
                float d11 = nk1 - 2.f * (hh[mt][nb][3] + md[mt][nb][3] * LO_IS);
                int s0 = mt * 2, s1 = mt * 2 + 1;
                if (d00 < bestv4[s0]) { bestv4[s0] = d00; besti4[s0] = code0; }
                if (d01 < bestv4[s0]) { bestv4[s0] = d01; besti4[s0] = code0 + 1; }
                if (d10 < bestv4[s1]) { bestv4[s1] = d10; besti4[s1] = code0; }
                if (d11 < bestv4[s1]) { bestv4[s1] = d11; besti4[s1] = code0 + 1; }
            }
        }
    }

    // lane-reduce across t (lanes 4g..4g+3 share a token row)
    #pragma unroll
    for (int s = 0; s < 4; s++) {
        #pragma unroll
        for (int m = 1; m <= 2; m <<= 1) {
            float v2 = __shfl_xor_sync(0xffffffffu, bestv4[s], m);
            int   i2 = __shfl_xor_sync(0xffffffffu, besti4[s], m);
            if (v2 < bestv4[s] || (v2 == bestv4[s] && i2 < besti4[s])) {
                bestv4[s] = v2; besti4[s] = i2;
            }
        }
    }
    if (t == 0) {
        #pragma unroll
        for (int s = 0; s < 4; s++) {
            int mt = s >> 1, h = s & 1;
            int tok = tg * 32 + mt * 16 + h * 8 + g;
            candv[tok * 2 + cg] = bestv4[s];
            candi[tok * 2 + cg] = besti4[s];
        }
    }
    __syncthreads();
    if (tid < MT) {
        float v0 = candv[tid * 2], v1 = candv[tid * 2 + 1];
        int   i0 = candi[tid * 2], i1 = candi[tid * 2 + 1];
        int bi;
        if (v1 < v0 || (v1 == v0 && i1 < i0)) bi = i1; else bi = i0;
        kf[tid] = bi;
        atomicAdd(&g_counts[bi], 1);
    }
    __syncthreads();

    // -------- fused gather + loss: 128 tokens x 256 channels ---------------
    {
        const int tok = tid & 127;
        const int ch0 = (tid >> 7) * 128;
        const int k   = kf[tok];
        const float4* crow = (const float4*)(cb + (size_t)k * C_DIM + ch0);
        const float* zp = zb + (size_t)ch0 * HW_DIM + tok;
        float* op = out + (size_t)b * (C_DIM * HW_DIM) + hw0
                        + (size_t)ch0 * HW_DIM + tok;
        float s = 0.f;
        #pragma unroll 8
        for (int j = 0; j < 32; j++) {
            float4 e = crow[j];
            int c = j * 4;
            float d0 = e.x - zp[(c + 0) * HW_DIM];
            float d1 = e.y - zp[(c + 1) * HW_DIM];
            float d2 = e.z - zp[(c + 2) * HW_DIM];
            float d3 = e.w - zp[(c + 3) * HW_DIM];
            s += d0 * d0 + d1 * d1 + d2 * d2 + d3 * d3;
            op[(c + 0) * HW_DIM] = e.x;
            op[(c + 1) * HW_DIM] = e.y;
            op[(c + 2) * HW_DIM] = e.z;
            op[(c + 3) * HW_DIM] = e.w;
        }
        red[tid] = s;
        __syncthreads();
        for (int off = 128; off > 0; off >>= 1) {
            if (tid < off) red[tid] += red[tid + off];
            __syncthreads();
        }
        if (tid == 0) g_partials[blockIdx.x] = red[0];
    }
}

// ---------------------------------------------------------------------------
__global__ void finalize_kernel(float* __restrict__ out, int out_size) {
    __shared__ float s1[1024];
    __shared__ float s2[1024];
    const int tid = threadIdx.x;
    float ls = (tid < NCTA) ? g_partials[tid] : 0.f;
    float p  = (float)g_counts[tid] * (1.0f / (float)N_TOK);
    float pc = fmaxf(p, 1e-10f);
    s1[tid] = ls;
    s2[tid] = pc * logf(pc);
    __syncthreads();
    for (int off = 512; off > 0; off >>= 1) {
        if (tid < off) { s1[tid] += s1[tid + off]; s2[tid] += s2[tid + off]; }
        __syncthreads();
    }
    if (tid == 0) {
        float mse = s1[0] * (1.0f / (float)Z_ELEMS);
        if (out_size >= Z_ELEMS + 1) out[Z_ELEMS]     = mse * (1.0f + BETA_F);
        if (out_size >= Z_ELEMS + 2) out[Z_ELEMS + 1] = expf(-s2[0]);
    }
}

// ---------------------------------------------------------------------------
extern "C" void kernel_launch(void* const* d_in, const int* in_sizes, int n_in,
                              void* d_out, int out_size) {
    const float* z  = (const float*)d_in[0];
    const float* cb = (const float*)d_in[1];
    float* out = (float*)d_out;

    cudaFuncSetAttribute(argmin_fused,
                         cudaFuncAttributeMaxDynamicSharedMemorySize, SMEM_TOTAL);

    prep_kernel<<<K_CODES, 256>>>(cb);
    argmin_fused<<<NCTA, 256, SMEM_TOTAL>>>(z, cb, out);
    finalize_kernel<<<1, 1024>>>(out, out_size);
}

// round 12
// speedup vs baseline: 1.5878x; 1.0213x over previous
#include <cuda_runtime.h>
#include <cuda_fp16.h>
#include <math.h>
#include <stdint.h>

// Shapes (fixed)
#define HW_DIM  1024
#define C_DIM   256
#define N_TOK   32768
#define K_CODES 1024
#define Z_ELEMS 8388608
#define BETA_F  0.25f

// tiling (R4-identical)
#define MT      128            // tokens per CTA
#define NCH     64             // codes per chunk
#define CHUNKS  (K_CODES / NCH)
#define KSTEPS  (C_DIM / 16)   // 16

// fp16 split scale (R4-identical)
#define LO_S    2048.0f
#define LO_IS   4.8828125e-4f

// smem layout (bytes) — R4-identical
#define ROWB    528
#define AH_OFF  0
#define AL_OFF  67584           // 128*528
#define BH_OFF  135168
#define BL_OFF  168960          // + 64*528
#define NS_OFF  202752          // 64 floats
#define CV_OFF  203008          // 128*2 floats
#define CI_OFF  204032          // 128*2 ints
#define SMEM_TOTAL 205056

#define GL_BLOCKS 1024          // gather: 32 tokens/block, 8 threads/token

static __device__ int   g_idx[N_TOK];
static __device__ int   g_counts[K_CODES];
static __device__ float g_norms[K_CODES];
static __device__ float g_partials[GL_BLOCKS];

// ---------------------------------------------------------------------------
__device__ __forceinline__ uint32_t smem_u32(const void* p) {
    uint32_t a;
    asm("{ .reg .u64 T; cvta.to.shared.u64 T, %1; cvt.u32.u64 %0, T; }"
        : "=r"(a) : "l"(p));
    return a;
}
__device__ __forceinline__ void ldsm4(uint32_t addr, uint32_t r[4]) {
    asm volatile("ldmatrix.sync.aligned.m8n8.x4.shared.b16 {%0,%1,%2,%3}, [%4];"
                 : "=r"(r[0]), "=r"(r[1]), "=r"(r[2]), "=r"(r[3]) : "r"(addr));
}
__device__ __forceinline__ void ldsm2(uint32_t addr, uint32_t r[2]) {
    asm volatile("ldmatrix.sync.aligned.m8n8.x2.shared.b16 {%0,%1}, [%2];"
                 : "=r"(r[0]), "=r"(r[1]) : "r"(addr));
}
__device__ __forceinline__ void mma_f16(float c[4], const uint32_t a[4],
                                        uint32_t b0, uint32_t b1) {
    asm volatile(
        "mma.sync.aligned.m16n8k16.row.col.f32.f16.f16.f32 "
        "{%0,%1,%2,%3}, {%4,%5,%6,%7}, {%8,%9}, {%0,%1,%2,%3};"
        : "+f"(c[0]), "+f"(c[1]), "+f"(c[2]), "+f"(c[3])
        : "r"(a[0]), "r"(a[1]), "r"(a[2]), "r"(a[3]), "r"(b0), "r"(b1));
}
__device__ __forceinline__ void split16(float a, __half& hi, __half& lo) {
    hi = __float2half_rn(a);
    lo = __float2half_rn((a - __half2float(hi)) * LO_S);
}

// ---------------------------------------------------------------------------
// prep: norms + zero counts (merged init) — measured 4.8us
__global__ void prep_kernel(const float* __restrict__ cb) {
    __shared__ float red[8];
    const int code = blockIdx.x;
    const int c    = threadIdx.x;
    float v = cb[code * C_DIM + c];
    float s = v * v;
    #pragma unroll
    for (int off = 16; off > 0; off >>= 1)
        s += __shfl_down_sync(0xffffffffu, s, off);
    if ((c & 31) == 0) red[c >> 5] = s;
    __syncthreads();
    if (c == 0) {
        float t = 0.f;
        #pragma unroll
        for (int i = 0; i < 8; i++) t += red[i];
        g_norms[code]  = t;
        g_counts[code] = 0;
    }
}

// ---------------------------------------------------------------------------
// R4 argmin kernel, verbatim (measured ~152us standalone).
// CTA: 128 tokens x all 1024 codes (16 chunks of 64).
// 8 warps = 4 token-groups x 2 code-groups; warp tile = 32 tok x 32 codes.
__global__ __launch_bounds__(256, 1)
void argmin_kernel(const float* __restrict__ z, const float* __restrict__ cb) {
    extern __shared__ char smem[];
    const uint32_t sb = smem_u32(smem);
    float* ns    = (float*)(smem + NS_OFF);
    float* candv = (float*)(smem + CV_OFF);
    int*   candi = (int*)(smem + CI_OFF);

    const int tid  = threadIdx.x;
    const int warp = tid >> 5;
    const int lane = tid & 31;
    const int tg   = warp & 3;
    const int cg   = warp >> 2;
    const int g    = lane >> 2;
    const int t    = lane & 3;
    const int l15  = lane & 15;

    const int n0  = blockIdx.x * MT;
    const int b   = n0 >> 10;
    const int hw0 = n0 & 1023;
    const float* zb = z + (size_t)b * (C_DIM * HW_DIM) + hw0;
    const float4* cb4 = (const float4*)cb;

    // stage A (128 tok x 256 c) as fp16 hi/lo, coalesced over tokens
    for (int it = 0; it < 128; it++) {
        int i  = it * 256 + tid;
        int tk = i & 127;
        int c  = i >> 7;
        float a = zb[(size_t)c * HW_DIM + tk];
        __half hi, lo;
        split16(a, hi, lo);
        *(__half*)(smem + AH_OFF + tk * ROWB + c * 2) = hi;
        *(__half*)(smem + AL_OFF + tk * ROWB + c * 2) = lo;
    }

    const uint32_t aH  = sb + AH_OFF + (uint32_t)((tg * 32 + l15) * ROWB + (lane >> 4) * 16);
    const uint32_t aL  = aH + (uint32_t)(AL_OFF - AH_OFF);
    const uint32_t bHb = sb + BH_OFF + (uint32_t)((cg * 32 + (l15 & 7)) * ROWB + (l15 >> 3) * 16);
    const uint32_t bLb = bHb + (uint32_t)(BL_OFF - BH_OFF);

    float bestv4[4];
    int   besti4[4];
    #pragma unroll
    for (int s = 0; s < 4; s++) { bestv4[s] = 3.4e38f; besti4[s] = 0; }

    for (int ch = 0; ch < CHUNKS; ch++) {
        const int k0c = ch * NCH;
        __syncthreads();   // protect B from previous chunk's readers
        // stage B chunk (64 codes x 256 c) fp16 hi/lo
        #pragma unroll
        for (int it = 0; it < 16; it++) {
            int i    = it * 256 + tid;
            int code = i >> 6;
            int j4   = i & 63;
            float4 v = cb4[(size_t)(k0c + code) * 64 + j4];
            __half h0, l0, h1, l1, h2, l2, h3, l3;
            split16(v.x, h0, l0); split16(v.y, h1, l1);
            split16(v.z, h2, l2); split16(v.w, h3, l3);
            __half2 hA = __halves2half2(h0, h1), hB = __halves2half2(h2, h3);
            __half2 lA = __halves2half2(l0, l1), lB = __halves2half2(l2, l3);
            uint32_t off = (uint32_t)(code * ROWB + j4 * 8);
            *(uint2*)(smem + BH_OFF + off) = make_uint2(*(uint32_t*)&hA, *(uint32_t*)&hB);
            *(uint2*)(smem + BL_OFF + off) = make_uint2(*(uint32_t*)&lA, *(uint32_t*)&lB);
        }
        if (tid < NCH) ns[tid] = g_norms[k0c + tid];
        __syncthreads();

        float hh[2][4][4], md[2][4][4];
        #pragma unroll
        for (int mt = 0; mt < 2; mt++)
            #pragma unroll
            for (int nb = 0; nb < 4; nb++)
                #pragma unroll
                for (int q = 0; q < 4; q++) { hh[mt][nb][q] = 0.f; md[mt][nb][q] = 0.f; }

        #pragma unroll 4
        for (int ks = 0; ks < KSTEPS; ks++) {
            uint32_t ah[2][4], al[2][4];
            #pragma unroll
            for (int mt = 0; mt < 2; mt++) {
                ldsm4(aH + (uint32_t)(mt * 16 * ROWB + ks * 32), ah[mt]);
                ldsm4(aL + (uint32_t)(mt * 16 * ROWB + ks * 32), al[mt]);
            }
            #pragma unroll
            for (int nb = 0; nb < 4; nb++) {
                uint32_t bh[2], bl[2];
                ldsm2(bHb + (uint32_t)(nb * 8 * ROWB + ks * 32), bh);
                ldsm2(bLb + (uint32_t)(nb * 8 * ROWB + ks * 32), bl);
                #pragma unroll
                for (int mt = 0; mt < 2; mt++) {
                    mma_f16(hh[mt][nb], ah[mt], bh[0], bh[1]);
                    mma_f16(md[mt][nb], ah[mt], bl[0], bl[1]);
                    mma_f16(md[mt][nb], al[mt], bh[0], bh[1]);
                }
            }
        }

        // epilogue: dist = |e|^2 - 2 (hh + md/2048)
        #pragma unroll
        for (int nb = 0; nb < 4; nb++) {
            int cl = cg * 32 + nb * 8 + 2 * t;
            float nk0 = ns[cl];
            float nk1 = ns[cl + 1];
            int code0 = k0c + cl;
            #pragma unroll
            for (int mt = 0; mt < 2; mt++) {
                float d00 = nk0 - 2.f * (hh[mt][nb][0] + md[mt][nb][0] * LO_IS);
                float d01 = nk1 - 2.f * (hh[mt][nb][1] + md[mt][nb][1] * LO_IS);
                float d10 = nk0 - 2.f * (hh[mt][nb][2] + md[mt][nb][2] * LO_IS);
                float d11 = nk1 - 2.f * (hh[mt][nb][3] + md[mt][nb][3] * LO_IS);
                int s0 = mt * 2, s1 = mt * 2 + 1;
                if (d00 < bestv4[s0]) { bestv4[s0] = d00; besti4[s0] = code0; }
                if (d01 < bestv4[s0]) { bestv4[s0] = d01; besti4[s0] = code0 + 1; }
                if (d10 < bestv4[s1]) { bestv4[s1] = d10; besti4[s1] = code0; }
                if (d11 < bestv4[s1]) { bestv4[s1] = d11; besti4[s1] = code0 + 1; }
            }
        }
    }

    // lane-reduce across t (lanes 4g..4g+3 share a token row)
    #pragma unroll
    for (int s = 0; s < 4; s++) {
        #pragma unroll
        for (int m = 1; m <= 2; m <<= 1) {
            float v2 = __shfl_xor_sync(0xffffffffu, bestv4[s], m);
            int   i2 = __shfl_xor_sync(0xffffffffu, besti4[s], m);
            if (v2 < bestv4[s] || (v2 == bestv4[s] && i2 < besti4[s])) {
                bestv4[s] = v2; besti4[s] = i2;
            }
        }
    }
    if (t == 0) {
        #pragma unroll
        for (int s = 0; s < 4; s++) {
            int mt = s >> 1, h = s & 1;
            int tok = tg * 32 + mt * 16 + h * 8 + g;
            candv[tok * 2 + cg] = bestv4[s];
            candi[tok * 2 + cg] = besti4[s];
        }
    }
    __syncthreads();
    if (tid < MT) {
        float v0 = candv[tid * 2], v1 = candv[tid * 2 + 1];
        int   i0 = candi[tid * 2], i1 = candi[tid * 2 + 1];
        int bi;
        if (v1 < v0 || (v1 == v0 && i1 < i0)) bi = i1; else bi = i0;
        g_idx[n0 + tid] = bi;
        atomicAdd(&g_counts[bi], 1);
    }
}

// ---------------------------------------------------------------------------
// gather: 1024 blocks, 32 tokens/block, 8 threads/token (32 channels each)
__global__ __launch_bounds__(256)
void gather_loss_kernel(const float* __restrict__ z,
                        const float* __restrict__ cb,
                        float* __restrict__ out) {
    __shared__ float red[256];
    const int tid = threadIdx.x;
    const int tok = blockIdx.x * 32 + (tid & 31);
    const int cc  = tid >> 5;           // channel chunk 0..7 (32 channels)
    const int k   = g_idx[tok];
    const int b   = tok >> 10;
    const int hw  = tok & 1023;
    const float4* c4p = (const float4*)cb + (size_t)k * 64 + cc * 8;
    const size_t base = (size_t)b * (C_DIM * HW_DIM) + (size_t)cc * 32 * HW_DIM + hw;
    const float* zp = z + base;
    float* op = out + base;
    float s = 0.f;
    #pragma unroll
    for (int j = 0; j < 8; j++) {
        float4 e = c4p[j];
        int c = j * 4;
        float d0 = e.x - zp[(c + 0) * HW_DIM];
        float d1 = e.y - zp[(c + 1) * HW_DIM];
        float d2 = e.z - zp[(c + 2) * HW_DIM];
        float d3 = e.w - zp[(c + 3) * HW_DIM];
        s += d0 * d0 + d1 * d1 + d2 * d2 + d3 * d3;
        op[(c + 0) * HW_DIM] = e.x;
        op[(c + 1) * HW_DIM] = e.y;
        op[(c + 2) * HW_DIM] = e.z;
        op[(c + 3) * HW_DIM] = e.w;
    }
    red[tid] = s;
    __syncthreads();
    for (int off = 128; off > 0; off >>= 1) {
        if (tid < off) red[tid] += red[tid + off];
        __syncthreads();
    }
    if (tid == 0) g_partials[blockIdx.x] = red[0];
}

// ---------------------------------------------------------------------------
__global__ void finalize_kernel(float* __restrict__ out, int out_size) {
    __shared__ float s1[1024];
    __shared__ float s2[1024];
    const int tid = threadIdx.x;
    float ls = g_partials[tid];          // GL_BLOCKS == 1024 == blockDim
    float p  = (float)g_counts[tid] * (1.0f / (float)N_TOK);
    float pc = fmaxf(p, 1e-10f);
    s1[tid] = ls;
    s2[tid] = pc * logf(pc);
    __syncthreads();
    for (int off = 512; off > 0; off >>= 1) {
        if (tid < off) { s1[tid] += s1[tid + off]; s2[tid] += s2[tid + off]; }
        __syncthreads();
    }
    if (tid == 0) {
        float mse = s1[0] * (1.0f / (float)Z_ELEMS);
        if (out_size >= Z_ELEMS + 1) out[Z_ELEMS]     = mse * (1.0f + BETA_F);
        if (out_size >= Z_ELEMS + 2) out[Z_ELEMS + 1] = expf(-s2[0]);
    }
}

// ---------------------------------------------------------------------------
extern "C" void kernel_launch(void* const* d_in, const int* in_sizes, int n_in,
                              void* d_out, int out_size) {
    const float* z  = (const float*)d_in[0];
    const float* cb = (const float*)d_in[1];
    float* out = (float*)d_out;

    cudaFuncSetAttribute(argmin_kernel,
                         cudaFuncAttributeMaxDynamicSharedMemorySize, SMEM_TOTAL);

    prep_kernel<<<K_CODES, 256>>>(cb);
    argmin_kernel<<<N_TOK / MT, 256, SMEM_TOTAL>>>(z, cb);
    gather_loss_kernel<<<GL_BLOCKS, 256>>>(z, cb, out);
    finalize_kernel<<<1, 1024>>>(out, out_size);
}

// round 13
// speedup vs baseline: 1.5959x; 1.0051x over previous
#include <cuda_runtime.h>
#include <cuda_fp16.h>
#include <math.h>
#include <stdint.h>

// Shapes (fixed)
#define HW_DIM  1024
#define C_DIM   256
#define N_TOK   32768
#define K_CODES 1024
#define Z_ELEMS 8388608
#define BETA_F  0.25f

// tiling (R4-identical)
#define MT      128            // tokens per CTA
#define NCH     64             // codes per chunk
#define CHUNKS  (K_CODES / NCH)
#define KSTEPS  (C_DIM / 16)   // 16

// fp16 split scale (R4-identical)
#define LO_S    2048.0f
#define LO_IS   4.8828125e-4f

// smem layout (bytes) — R4-identical
#define ROWB    528
#define AH_OFF  0
#define AL_OFF  67584           // 128*528
#define BH_OFF  135168
#define BL_OFF  168960          // + 64*528
#define NS_OFF  202752          // 64 floats
#define CV_OFF  203008          // 128*2 floats
#define CI_OFF  204032          // 128*2 ints
#define SMEM_TOTAL 205056

#define GL_BLOCKS 1024          // gather: 32 tokens/block, 8 threads/token

static __device__ int   g_idx[N_TOK];
static __device__ int   g_counts[K_CODES];
static __device__ float g_norms[K_CODES];
static __device__ float g_partials[GL_BLOCKS];
static __device__ int   g_done;

// ---------------------------------------------------------------------------
__device__ __forceinline__ uint32_t smem_u32(const void* p) {
    uint32_t a;
    asm("{ .reg .u64 T; cvta.to.shared.u64 T, %1; cvt.u32.u64 %0, T; }"
        : "=r"(a) : "l"(p));
    return a;
}
__device__ __forceinline__ void ldsm4(uint32_t addr, uint32_t r[4]) {
    asm volatile("ldmatrix.sync.aligned.m8n8.x4.shared.b16 {%0,%1,%2,%3}, [%4];"
                 : "=r"(r[0]), "=r"(r[1]), "=r"(r[2]), "=r"(r[3]) : "r"(addr));
}
__device__ __forceinline__ void ldsm2(uint32_t addr, uint32_t r[2]) {
    asm volatile("ldmatrix.sync.aligned.m8n8.x2.shared.b16 {%0,%1}, [%2];"
                 : "=r"(r[0]), "=r"(r[1]) : "r"(addr));
}
__device__ __forceinline__ void mma_f16(float c[4], const uint32_t a[4],
                                        uint32_t b0, uint32_t b1) {
    asm volatile(
        "mma.sync.aligned.m16n8k16.row.col.f32.f16.f16.f32 "
        "{%0,%1,%2,%3}, {%4,%5,%6,%7}, {%8,%9}, {%0,%1,%2,%3};"
        : "+f"(c[0]), "+f"(c[1]), "+f"(c[2]), "+f"(c[3])
        : "r"(a[0]), "r"(a[1]), "r"(a[2]), "r"(a[3]), "r"(b0), "r"(b1));
}
__device__ __forceinline__ void split16(float a, __half& hi, __half& lo) {
    hi = __float2half_rn(a);
    lo = __float2half_rn((a - __half2float(hi)) * LO_S);
}

// ---------------------------------------------------------------------------
// prep: warp-per-code norms + zero counts + reset done counter
__global__ void prep_kernel(const float* __restrict__ cb) {
    const int code = blockIdx.x * 8 + (threadIdx.x >> 5);
    const int lane = threadIdx.x & 31;
    const float* row = cb + code * C_DIM;
    float s = 0.f;
    #pragma unroll
    for (int c = lane; c < C_DIM; c += 32) { float v = row[c]; s += v * v; }
    #pragma unroll
    for (int off = 16; off > 0; off >>= 1)
        s += __shfl_down_sync(0xffffffffu, s, off);
    if (lane == 0) {
        g_norms[code]  = s;
        g_counts[code] = 0;
        if (code == 0) g_done = 0;
    }
}

// ---------------------------------------------------------------------------
// R4 argmin kernel, verbatim (measured ~152us standalone).
__global__ __launch_bounds__(256, 1)
void argmin_kernel(const float* __restrict__ z, const float* __restrict__ cb) {
    extern __shared__ char smem[];
    const uint32_t sb = smem_u32(smem);
    float* ns    = (float*)(smem + NS_OFF);
    float* candv = (float*)(smem + CV_OFF);
    int*   candi = (int*)(smem + CI_OFF);

    const int tid  = threadIdx.x;
    const int warp = tid >> 5;
    const int lane = tid & 31;
    const int tg   = warp & 3;
    const int cg   = warp >> 2;
    const int g    = lane >> 2;
    const int t    = lane & 3;
    const int l15  = lane & 15;

    const int n0  = blockIdx.x * MT;
    const int b   = n0 >> 10;
    const int hw0 = n0 & 1023;
    const float* zb = z + (size_t)b * (C_DIM * HW_DIM) + hw0;
    const float4* cb4 = (const float4*)cb;

    for (int it = 0; it < 128; it++) {
        int i  = it * 256 + tid;
        int tk = i & 127;
        int c  = i >> 7;
        float a = zb[(size_t)c * HW_DIM + tk];
        __half hi, lo;
        split16(a, hi, lo);
        *(__half*)(smem + AH_OFF + tk * ROWB + c * 2) = hi;
        *(__half*)(smem + AL_OFF + tk * ROWB + c * 2) = lo;
    }

    const uint32_t aH  = sb + AH_OFF + (uint32_t)((tg * 32 + l15) * ROWB + (lane >> 4) * 16);
    const uint32_t aL  = aH + (uint32_t)(AL_OFF - AH_OFF);
    const uint32_t bHb = sb + BH_OFF + (uint32_t)((cg * 32 + (l15 & 7)) * ROWB + (l15 >> 3) * 16);
    const uint32_t bLb = bHb + (uint32_t)(BL_OFF - BH_OFF);

    float bestv4[4];
    int   besti4[4];
    #pragma unroll
    for (int s = 0; s < 4; s++) { bestv4[s] = 3.4e38f; besti4[s] = 0; }

    for (int ch = 0; ch < CHUNKS; ch++) {
        const int k0c = ch * NCH;
        __syncthreads();
        #pragma unroll
        for (int it = 0; it < 16; it++) {
            int i    = it * 256 + tid;
            int code = i >> 6;
            int j4   = i & 63;
            float4 v = cb4[(size_t)(k0c + code) * 64 + j4];
            __half h0, l0, h1, l1, h2, l2, h3, l3;
            split16(v.x, h0, l0); split16(v.y, h1, l1);
            split16(v.z, h2, l2); split16(v.w, h3, l3);
            __half2 hA = __halves2half2(h0, h1), hB = __halves2half2(h2, h3);
            __half2 lA = __halves2half2(l0, l1), lB = __halves2half2(l2, l3);
            uint32_t off = (uint32_t)(code * ROWB + j4 * 8);
            *(uint2*)(smem + BH_OFF + off) = make_uint2(*(uint32_t*)&hA, *(uint32_t*)&hB);
            *(uint2*)(smem + BL_OFF + off) = make_uint2(*(uint32_t*)&lA, *(uint32_t*)&lB);
        }
        if (tid < NCH) ns[tid] = g_norms[k0c + tid];
        __syncthreads();

        float hh[2][4][4], md[2][4][4];
        #pragma unroll
        for (int mt = 0; mt < 2; mt++)
            #pragma unroll
            for (int nb = 0; nb < 4; nb++)
                #pragma unroll
                for (int q = 0; q < 4; q++) { hh[mt][nb][q] = 0.f; md[mt][nb][q] = 0.f; }

        #pragma unroll 4
        for (int ks = 0; ks < KSTEPS; ks++) {
            uint32_t ah[2][4], al[2][4];
            #pragma unroll
            for (int mt = 0; mt < 2; mt++) {
                ldsm4(aH + (uint32_t)(mt * 16 * ROWB + ks * 32), ah[mt]);
                ldsm4(aL + (uint32_t)(mt * 16 * ROWB + ks * 32), al[mt]);
            }
            #pragma unroll
            for (int nb = 0; nb < 4; nb++) {
                uint32_t bh[2], bl[2];
                ldsm2(bHb + (uint32_t)(nb * 8 * ROWB + ks * 32), bh);
                ldsm2(bLb + (uint32_t)(nb * 8 * ROWB + ks * 32), bl);
                #pragma unroll
                for (int mt = 0; mt < 2; mt++) {
                    mma_f16(hh[mt][nb], ah[mt], bh[0], bh[1]);
                    mma_f16(md[mt][nb], ah[mt], bl[0], bl[1]);
                    mma_f16(md[mt][nb], al[mt], bh[0], bh[1]);
                }
            }
        }

        #pragma unroll
        for (int nb = 0; nb < 4; nb++) {
            int cl = cg * 32 + nb * 8 + 2 * t;
            float nk0 = ns[cl];
            float nk1 = ns[cl + 1];
            int code0 = k0c + cl;
            #pragma unroll
            for (int mt = 0; mt < 2; mt++) {
                float d00 = nk0 - 2.f * (hh[mt][nb][0] + md[mt][nb][0] * LO_IS);
                float d01 = nk1 - 2.f * (hh[mt][nb][1] + md[mt][nb][1] * LO_IS);
                float d10 = nk0 - 2.f * (hh[mt][nb][2] + md[mt][nb][2] * LO_IS);
                float d11 = nk1 - 2.f * (hh[mt][nb][3] + md[mt][nb][3] * LO_IS);
                int s0 = mt * 2, s1 = mt * 2 + 1;
                if (d00 < bestv4[s0]) { bestv4[s0] = d00; besti4[s0] = code0; }
                if (d01 < bestv4[s0]) { bestv4[s0] = d01; besti4[s0] = code0 + 1; }
                if (d10 < bestv4[s1]) { bestv4[s1] = d10; besti4[s1] = code0; }
                if (d11 < bestv4[s1]) { bestv4[s1] = d11; besti4[s1] = code0 + 1; }
            }
        }
    }

    #pragma unroll
    for (int s = 0; s < 4; s++) {
        #pragma unroll
        for (int m = 1; m <= 2; m <<= 1) {
            float v2 = __shfl_xor_sync(0xffffffffu, bestv4[s], m);
            int   i2 = __shfl_xor_sync(0xffffffffu, besti4[s], m);
            if (v2 < bestv4[s] || (v2 == bestv4[s] && i2 < besti4[s])) {
                bestv4[s] = v2; besti4[s] = i2;
            }
        }
    }
    if (t == 0) {
        #pragma unroll
        for (int s = 0; s < 4; s++) {
            int mt = s >> 1, h = s & 1;
            int tok = tg * 32 + mt * 16 + h * 8 + g;
            candv[tok * 2 + cg] = bestv4[s];
            candi[tok * 2 + cg] = besti4[s];
        }
    }
    __syncthreads();
    if (tid < MT) {
        float v0 = candv[tid * 2], v1 = candv[tid * 2 + 1];
        int   i0 = candi[tid * 2], i1 = candi[tid * 2 + 1];
        int bi;
        if (v1 < v0 || (v1 == v0 && i1 < i0)) bi = i1; else bi = i0;
        g_idx[n0 + tid] = bi;
        atomicAdd(&g_counts[bi], 1);
    }
}

// ---------------------------------------------------------------------------
// gather + fused finalize: 1024 blocks, 32 tokens/block, 8 threads/token.
// Last block to finish performs the deterministic final reduction.
__global__ __launch_bounds__(256)
void gather_loss_kernel(const float* __restrict__ z,
                        const float* __restrict__ cb,
                        float* __restrict__ out, int out_size) {
    __shared__ float red[256];
    __shared__ float red2[256];
    __shared__ bool  amLast;
    const int tid = threadIdx.x;
    const int tok = blockIdx.x * 32 + (tid & 31);
    const int cc  = tid >> 5;           // channel chunk 0..7 (32 channels)
    const int k   = g_idx[tok];
    const int b   = tok >> 10;
    const int hw  = tok & 1023;
    const float4* c4p = (const float4*)cb + (size_t)k * 64 + cc * 8;
    const size_t base = (size_t)b * (C_DIM * HW_DIM) + (size_t)cc * 32 * HW_DIM + hw;
    const float* zp = z + base;
    float* op = out + base;
    float s = 0.f;
    #pragma unroll
    for (int j = 0; j < 8; j++) {
        float4 e = c4p[j];
        int c = j * 4;
        float d0 = e.x - zp[(c + 0) * HW_DIM];
        float d1 = e.y - zp[(c + 1) * HW_DIM];
        float d2 = e.z - zp[(c + 2) * HW_DIM];
        float d3 = e.w - zp[(c + 3) * HW_DIM];
        s += d0 * d0 + d1 * d1 + d2 * d2 + d3 * d3;
        op[(c + 0) * HW_DIM] = e.x;
        op[(c + 1) * HW_DIM] = e.y;
        op[(c + 2) * HW_DIM] = e.z;
        op[(c + 3) * HW_DIM] = e.w;
    }
    red[tid] = s;
    __syncthreads();
    for (int off = 128; off > 0; off >>= 1) {
        if (tid < off) red[tid] += red[tid + off];
        __syncthreads();
    }
    if (tid == 0) {
        g_partials[blockIdx.x] = red[0];
        __threadfence();
        amLast = (atomicAdd(&g_done, 1) == GL_BLOCKS - 1);
    }
    __syncthreads();

    if (amLast) {
        // deterministic fixed-tree: 4 partials + 4 codes per thread
        float ls = g_partials[tid] + g_partials[tid + 256]
                 + g_partials[tid + 512] + g_partials[tid + 768];
        float en = 0.f;
        #pragma unroll
        for (int j = 0; j < 4; j++) {
            float p  = (float)g_counts[tid * 4 + j] * (1.0f / (float)N_TOK);
            float pc = fmaxf(p, 1e-10f);
            en += pc * logf(pc);
        }
        red[tid]  = ls;
        red2[tid] = en;
        __syncthreads();
        for (int off = 128; off > 0; off >>= 1) {
            if (tid < off) { red[tid] += red[tid + off]; red2[tid] += red2[tid + off]; }
            __syncthreads();
        }
        if (tid == 0) {
            float mse = red[0] * (1.0f / (float)Z_ELEMS);
            if (out_size >= Z_ELEMS + 1) out[Z_ELEMS]     = mse * (1.0f + BETA_F);
            if (out_size >= Z_ELEMS + 2) out[Z_ELEMS + 1] = expf(-red2[0]);
        }
    }
}

// ---------------------------------------------------------------------------
extern "C" void kernel_launch(void* const* d_in, const int* in_sizes, int n_in,
                              void* d_out, int out_size) {
    const float* z  = (const float*)d_in[0];
    const float* cb = (const float*)d_in[1];
    float* out = (float*)d_out;

    cudaFuncSetAttribute(argmin_kernel,
                         cudaFuncAttributeMaxDynamicSharedMemorySize, SMEM_TOTAL);

    prep_kernel<<<K_CODES / 8, 256>>>(cb);
    argmin_kernel<<<N_TOK / MT, 256, SMEM_TOTAL>>>(z, cb);
    gather_loss_kernel<<<GL_BLOCKS, 256>>>(z, cb, out, out_size);
}